// round 17
// baseline (speedup 1.0000x reference)
#include <cuda_runtime.h>
#include <cuda_bf16.h>
#include <cstdint>

// FlaxHouseholderRoPE: B=2, S=4096, H=32, D=128, R=2, fp32. SINGLE launch,
// self-bootstrapping hybrid:
//  - 520 builder blocks (wave-1) fill g_tab (cos/sin table) and g_u
//    (normalized reflectors), release via fence+atomicAdd, exit.
//  - 32768 consumer blocks check the flag ONCE (acquire, no spin):
//      ready  -> read u/cs via plain coherent LDG (L1-cached; lines can only
//                hold post-release fills since nobody touches them earlier;
//                address-dependency `+ (ready>>10)` defeats speculation)
//      !ready -> compute u and cs in-thread with code byte-identical to the
//                builders => output bits identical on both paths.
//  - Counters reset by last block => identical work every graph replay.

#define SS 4096
#define HH 32
#define NVEC (2 * SS * HH)        // 262144 vectors per tensor
#define NCONS (NVEC / 8)          // 32768 consumer blocks
#define NB_TAB 512
#define NBUILD (NB_TAB + 8)       // 520 builder blocks
#define GRIDTOT (NCONS + NBUILD)

__device__ float4 g_tab[SS * 32];      // (cos,sin,cos,sin) per (s,lane)
__device__ float4 g_u[HH * 2 * 32];    // v * sqrt(2/(|v|^2+eps))
__device__ int    g_ready;             // zero-initialized
__device__ int    g_done;

// inv_freq = 10000^(-i/64): compile-time double-precision table
constexpr double R64 = 0.8659643233600653;   // 10000^(-1/64)
constexpr double rpow(int i) {
    double v = 1.0;
    for (int j = 0; j < i; ++j) v *= R64;
    return v;
}
#define FQ(l) { (float)rpow(2*(l)), (float)rpow(2*(l)+1) }
__device__ const float2 g_freq[32] = {
    FQ(0),  FQ(1),  FQ(2),  FQ(3),  FQ(4),  FQ(5),  FQ(6),  FQ(7),
    FQ(8),  FQ(9),  FQ(10), FQ(11), FQ(12), FQ(13), FQ(14), FQ(15),
    FQ(16), FQ(17), FQ(18), FQ(19), FQ(20), FQ(21), FQ(22), FQ(23),
    FQ(24), FQ(25), FQ(26), FQ(27), FQ(28), FQ(29), FQ(30), FQ(31)
};

__device__ __forceinline__ float dot4(float4 a, float4 b) {
    return a.x * b.x + a.y * b.y + a.z * b.z + a.w * b.w;
}

// sincos for a <= 4096: 2-term Cody-Waite + MUFU (err ~1e-6 rad; tol 1e-3)
__device__ __forceinline__ float2 fast_sincos(float a) {
    const float INV2PI = 0.15915494309189535f;
    const float C1 = 6.28125f;                    // n*C1 exact for n <= 652
    const float C2 = 1.9353071795864769e-3f;      // 2*pi - C1
    const float n = rintf(a * INV2PI);
    float r = fmaf(-n, C1, a);
    r = fmaf(-n, C2, r);
    return make_float2(__cosf(r), __sinf(r));
}

// normalize one reflector row slice: MUST stay bit-identical between builder
// and fallback (single-value 5-step xor butterfly, then sqrt scale)
__device__ __forceinline__ float4 norm_row(float4 v) {
    float sq = dot4(v, v);
    #pragma unroll
    for (int o = 16; o; o >>= 1) sq += __shfl_xor_sync(0xffffffffu, sq, o);
    const float sc = sqrtf(2.0f / (sq + 1e-6f));
    return make_float4(v.x * sc, v.y * sc, v.z * sc, v.w * sc);
}

__global__ __launch_bounds__(256, 8)
void hh_rope_kernel(const float* __restrict__ q,
                    const float* __restrict__ k,
                    const float* __restrict__ pos,
                    const float* __restrict__ refl,
                    float* __restrict__ out) {
    const int tid  = threadIdx.x;
    const int warp = tid >> 5;
    const int lane = tid & 31;

    // ================= builder blocks =================
    if (blockIdx.x < NBUILD) {
        if (blockIdx.x < NB_TAB) {
            const int j = blockIdx.x * 256 + tid;   // 0..131071
            const int s = j >> 5;
            const int t = j & 31;
            const float  p  = pos[s];
            const float2 f  = g_freq[t];
            const float2 c0 = fast_sincos(p * f.x);
            const float2 c1 = fast_sincos(p * f.y);
            g_tab[j] = make_float4(c0.x, c0.y, c1.x, c1.y);
        } else {
            const int row = (blockIdx.x - NB_TAB) * 8 + warp;   // 0..63
            const float4 v = __ldg(reinterpret_cast<const float4*>(refl)
                                   + row * 32 + lane);
            g_u[row * 32 + lane] = norm_row(v);
        }
        __syncthreads();
        __threadfence();
        if (tid == 0) {
            atomicAdd(&g_ready, 1);                 // release (after fence)
            const int d = atomicAdd(&g_done, 1);
            if (d == GRIDTOT - 1) { g_done = 0; g_ready = 0; __threadfence(); }
        }
        return;
    }

    // ================= consumer blocks =================
    const int idx = (int)(blockIdx.x - NBUILD) * 8 + warp;   // (b*S+s)*H + h
    const int h   = idx & (HH - 1);
    const int s   = (idx >> 5) & (SS - 1);

    // streamed loads FIRST (coalesced LDG.128, evict-first)
    const size_t off = (size_t)idx * 32 + lane;
    float4 xq = __ldcs(reinterpret_cast<const float4*>(q) + off);
    float4 xk = __ldcs(reinterpret_cast<const float4*>(k) + off);

    // one acquire-load of the flag (no spin)
    int ready;
    asm volatile("ld.acquire.gpu.b32 %0, [%1];"
                 : "=r"(ready) : "l"(&g_ready) : "memory");

    float4 u0, u1, cs;
    if (ready >= NBUILD) {
        // fast path: L1-cached coherent loads. ready <= NBUILD < 1024 so
        // dep == 0, but the compiler can't prove it -> address dependency
        // on the acquire result prevents speculative hoisting.
        const int dep = ready >> 10;
        u0 = g_u[(h * 2 + 0) * 32 + lane + dep];
        u1 = g_u[(h * 2 + 1) * 32 + lane + dep];
        cs = g_tab[s * 32 + lane + dep];
    } else {
        // slow path (wave-1 only): byte-identical math to the builders
        u0 = norm_row(__ldg(reinterpret_cast<const float4*>(refl)
                            + (h * 2 + 0) * 32 + lane));
        u1 = norm_row(__ldg(reinterpret_cast<const float4*>(refl)
                            + (h * 2 + 1) * 32 + lane));
        const float  p  = pos[s];
        const float2 f  = g_freq[lane];
        const float2 c0 = fast_sincos(p * f.x);
        const float2 c1 = fast_sincos(p * f.y);
        cs = make_float4(c0.x, c0.y, c1.x, c1.y);
    }

    // ---- two normalized-Householder reflections (identical on both paths) ----
    {
        float dq = dot4(xq, u0);
        float dk = dot4(xk, u0);
        #pragma unroll
        for (int o = 16; o; o >>= 1) {
            dq += __shfl_xor_sync(0xffffffffu, dq, o);
            dk += __shfl_xor_sync(0xffffffffu, dk, o);
        }
        xq.x -= dq * u0.x;  xq.y -= dq * u0.y;  xq.z -= dq * u0.z;  xq.w -= dq * u0.w;
        xk.x -= dk * u0.x;  xk.y -= dk * u0.y;  xk.z -= dk * u0.z;  xk.w -= dk * u0.w;
    }
    {
        float dq = dot4(xq, u1);
        float dk = dot4(xk, u1);
        #pragma unroll
        for (int o = 16; o; o >>= 1) {
            dq += __shfl_xor_sync(0xffffffffu, dq, o);
            dk += __shfl_xor_sync(0xffffffffu, dk, o);
        }
        xq.x -= dq * u1.x;  xq.y -= dq * u1.y;  xq.z -= dq * u1.z;  xq.w -= dq * u1.w;
        xk.x -= dk * u1.x;  xk.y -= dk * u1.y;  xk.z -= dk * u1.z;  xk.w -= dk * u1.w;
    }

    // ---- RoPE ----
    float4 oq, ok;
    oq.x = xq.x * cs.x - xq.y * cs.y;
    oq.y = xq.x * cs.y + xq.y * cs.x;
    oq.z = xq.z * cs.z - xq.w * cs.w;
    oq.w = xq.z * cs.w + xq.w * cs.z;
    ok.x = xk.x * cs.x - xk.y * cs.y;
    ok.y = xk.x * cs.y + xk.y * cs.x;
    ok.z = xk.z * cs.z - xk.w * cs.w;
    ok.w = xk.z * cs.w + xk.w * cs.z;

    float4* out4 = reinterpret_cast<float4*>(out);
    __stcs(out4 + off, oq);                              // q half
    __stcs(out4 + (size_t)NVEC * 32 + off, ok);          // k half

    // ---- replay reset (last of all GRIDTOT blocks) ----
    if (tid == 0) {
        const int d = atomicAdd(&g_done, 1);
        if (d == GRIDTOT - 1) { g_done = 0; g_ready = 0; __threadfence(); }
    }
}

extern "C" void kernel_launch(void* const* d_in, const int* in_sizes, int n_in,
                              void* d_out, int out_size) {
    const float* q    = (const float*)d_in[0];
    const float* k    = (const float*)d_in[1];
    const float* pos  = (const float*)d_in[2];
    const float* refl = (const float*)d_in[3];
    float* out = (float*)d_out;

    hh_rope_kernel<<<GRIDTOT, 256>>>(q, k, pos, refl, out);
}